// round 3
// baseline (speedup 1.0000x reference)
#include <cuda_runtime.h>
#include <math.h>

#define BATCH 2
#define NQ    8192
#define NPT   4096
#define DIM   128
#define KNN   16
#define NFEAT 33
#define NSLOT 17   // KNN + 1 global slot

// ---- scratch (static __device__ — no allocations allowed) ----
__device__ float g_kproj[BATCH * NPT * DIM];
__device__ float g_vproj[BATCH * NPT * DIM];
__device__ float g_q [BATCH * DIM];
__device__ float g_kg[BATCH * DIM];
__device__ float g_vg[BATCH * DIM];

// ============================================================
// Kernel 0: global-latent projections  q = lat@Wq, kg = lat@Wkg, vg = lat@Wvg
// grid = BATCH, block = DIM
// ============================================================
__global__ void proj_global_kernel(const float* __restrict__ lat,
                                   const float* __restrict__ wq,
                                   const float* __restrict__ wkg,
                                   const float* __restrict__ wvg) {
    int b = blockIdx.x;
    int c = threadIdx.x;
    __shared__ float l[DIM];
    l[c] = lat[b * DIM + c];
    __syncthreads();
    float aq = 0.f, ak = 0.f, av = 0.f;
    #pragma unroll 4
    for (int k = 0; k < DIM; k++) {
        float lv = l[k];
        aq += lv * wq [k * DIM + c];
        ak += lv * wkg[k * DIM + c];
        av += lv * wvg[k * DIM + c];
    }
    g_q [b * DIM + c] = aq;
    g_kg[b * DIM + c] = ak;
    g_vg[b * DIM + c] = av;
}

// ============================================================
// Kernel 1: point projections  kproj = points@Wk, vproj = points@Wv
// grid = BATCH*NPT/ROWS, block = DIM; thread c = output column
// ============================================================
#define PROWS 16
__global__ __launch_bounds__(DIM)
void proj_points_kernel(const float* __restrict__ points,
                        const float* __restrict__ wks,
                        const float* __restrict__ wvs) {
    int c = threadIdx.x;
    int row0 = blockIdx.x * PROWS;
    __shared__ float p_sh[PROWS * DIM];
    for (int i = c; i < PROWS * DIM; i += DIM)
        p_sh[i] = points[row0 * DIM + i];
    __syncthreads();

    float ak[PROWS], av[PROWS];
    #pragma unroll
    for (int r = 0; r < PROWS; r++) { ak[r] = 0.f; av[r] = 0.f; }

    for (int k = 0; k < DIM; k++) {
        float wk = wks[k * DIM + c];
        float wv = wvs[k * DIM + c];
        #pragma unroll
        for (int r = 0; r < PROWS; r++) {
            float p = p_sh[r * DIM + k];
            ak[r] += p * wk;
            av[r] += p * wv;
        }
    }
    #pragma unroll
    for (int r = 0; r < PROWS; r++) {
        g_kproj[(row0 + r) * DIM + c] = ak[r];
        g_vproj[(row0 + r) * DIM + c] = av[r];
    }
}

// ============================================================
// Kernel 2: main — one block per query, thread c = channel
// ============================================================
__global__ __launch_bounds__(DIM)
void main_kernel(const float* __restrict__ xyz_q,
                 const float* __restrict__ xyz,
                 const float* __restrict__ gw1, const float* __restrict__ gb1,
                 const float* __restrict__ gw2, const float* __restrict__ gb2,
                 const float* __restrict__ pe_w, const float* __restrict__ pe_b,
                 float* __restrict__ out) {
    // shared pool: pe[16*128] | h[17*128] | t[17*128] | emb[16*33]
    // kNN candidate lists (128*16 dist + 128*16 idx = 4096 words) alias the front.
    __shared__ float pool[2048 + 2176 + 2176 + 528];
    __shared__ int   knn_idx[KNN];
    float* pe_sh  = pool;
    float* h_sh   = pool + 2048;
    float* t_sh   = pool + 2048 + 2176;
    float* emb_sh = pool + 2048 + 2176 + 2176;

    const int tid = threadIdx.x;
    const int bq  = blockIdx.x;
    const int b   = bq / NQ;

    const float qx = xyz_q[bq * 2 + 0];
    const float qy = xyz_q[bq * 2 + 1];
    const float* xyzb = xyz + b * NPT * 3;

    // ---------------- kNN: per-thread top-16 over 32 points ----------------
    float bd[KNN]; int bi[KNN];
    #pragma unroll
    for (int k = 0; k < KNN; k++) { bd[k] = 3.4e38f; bi[k] = 0; }

    for (int p = tid; p < NPT; p += DIM) {
        float dx = qx - xyzb[p * 3 + 0];
        float dy = qy - xyzb[p * 3 + 1];
        float d  = dx * dx + dy * dy;
        if (d < bd[KNN - 1]) {
            bd[KNN - 1] = d; bi[KNN - 1] = p;
            #pragma unroll
            for (int s = KNN - 1; s > 0; s--) {
                if (bd[s] < bd[s - 1]) {
                    float td = bd[s]; bd[s] = bd[s - 1]; bd[s - 1] = td;
                    int   ti = bi[s]; bi[s] = bi[s - 1]; bi[s - 1] = ti;
                }
            }
        }
    }

    float* cd = pool;                 // 2048 floats
    int*   ci = (int*)(pool + 2048);  // 2048 ints
    #pragma unroll
    for (int k = 0; k < KNN; k++) { cd[tid * KNN + k] = bd[k]; ci[tid * KNN + k] = bi[k]; }
    __syncthreads();

    // tree merge of 128 sorted 16-lists
    for (int stride = 64; stride >= 1; stride >>= 1) {
        if (tid < stride) {
            int a0 = tid * KNN, b0 = (tid + stride) * KNN;
            int ia = 0, ib = 0;
            float od[KNN]; int oi[KNN];
            #pragma unroll
            for (int k = 0; k < KNN; k++) {
                float da = (ia < KNN) ? cd[a0 + ia] : 3.4e38f;
                float db = (ib < KNN) ? cd[b0 + ib] : 3.4e38f;
                if (da <= db) { od[k] = da; oi[k] = ci[a0 + ia]; ia++; }
                else          { od[k] = db; oi[k] = ci[b0 + ib]; ib++; }
            }
            #pragma unroll
            for (int k = 0; k < KNN; k++) { cd[a0 + k] = od[k]; ci[a0 + k] = oi[k]; }
        }
        __syncthreads();
    }
    if (tid < KNN) knn_idx[tid] = ci[tid];
    __syncthreads();

    // ---------------- positional embeddings (16 neighbors x 33 feats) ------
    if (tid < KNN * 3) {
        int j = tid / 3, comp = tid - j * 3;
        int pidx = knn_idx[j];
        float v;
        if      (comp == 0) v = qx - xyzb[pidx * 3 + 0];
        else if (comp == 1) v = qy - xyzb[pidx * 3 + 1];
        else                v = xyzb[pidx * 3 + 2];
        emb_sh[j * NFEAT + comp] = v;
        #pragma unroll
        for (int f = 0; f < 5; f++) {
            float fr = 1.0f + 7.75f * (float)f;   // linspace(1, 32, 5)
            float s, co;
            sincosf(v * fr, &s, &co);
            emb_sh[j * NFEAT + 3 + 6 * f + comp] = s;
            emb_sh[j * NFEAT + 6 + 6 * f + comp] = co;
        }
    }
    __syncthreads();

    const int c = tid;

    // ---------------- pos_encode = emb @ pe_w + pe_b ------------------------
    float pa[KNN];
    {
        float peb = pe_b[c];
        #pragma unroll
        for (int j = 0; j < KNN; j++) pa[j] = peb;
        for (int f = 0; f < NFEAT; f++) {
            float w = pe_w[f * DIM + c];
            #pragma unroll
            for (int j = 0; j < KNN; j++) pa[j] += emb_sh[j * NFEAT + f] * w;
        }
    }

    // ---------------- h = q - k + pe  (17 slots) ----------------------------
    const float qc = g_q[b * DIM + c];
    #pragma unroll
    for (int j = 0; j < KNN; j++) {
        pe_sh[j * DIM + c] = pa[j];
        int pidx = knn_idx[j];
        float kj = g_kproj[(b * NPT + pidx) * DIM + c];
        h_sh[j * DIM + c] = qc - kj + pa[j];
    }
    h_sh[KNN * DIM + c] = qc - g_kg[b * DIM + c];
    __syncthreads();

    // ---------------- GEMM1: t = relu(h @ gw1 + gb1) ------------------------
    float acc[NSLOT];
    {
        float b1 = gb1[c];
        #pragma unroll
        for (int j = 0; j < NSLOT; j++) acc[j] = b1;
        for (int k = 0; k < DIM; k += 4) {
            float w0 = gw1[(k + 0) * DIM + c];
            float w1 = gw1[(k + 1) * DIM + c];
            float w2 = gw1[(k + 2) * DIM + c];
            float w3 = gw1[(k + 3) * DIM + c];
            #pragma unroll
            for (int j = 0; j < NSLOT; j++) {
                float4 hv = *(const float4*)&h_sh[j * DIM + k];
                acc[j] += hv.x * w0 + hv.y * w1 + hv.z * w2 + hv.w * w3;
            }
        }
        #pragma unroll
        for (int j = 0; j < NSLOT; j++) t_sh[j * DIM + c] = fmaxf(acc[j], 0.0f);
    }
    __syncthreads();

    // ---------------- GEMM2: s = t @ gw2 + gb2 ------------------------------
    {
        float b2 = gb2[c];
        #pragma unroll
        for (int j = 0; j < NSLOT; j++) acc[j] = b2;
        for (int k = 0; k < DIM; k += 4) {
            float w0 = gw2[(k + 0) * DIM + c];
            float w1 = gw2[(k + 1) * DIM + c];
            float w2 = gw2[(k + 2) * DIM + c];
            float w3 = gw2[(k + 3) * DIM + c];
            #pragma unroll
            for (int j = 0; j < NSLOT; j++) {
                float4 tv = *(const float4*)&t_sh[j * DIM + k];
                acc[j] += tv.x * w0 + tv.y * w1 + tv.z * w2 + tv.w * w3;
            }
        }
    }

    // ---------------- softmax over the 17 slots (per channel) ---------------
    float m = acc[0];
    #pragma unroll
    for (int j = 1; j < NSLOT; j++) m = fmaxf(m, acc[j]);
    float ssum = 0.f;
    #pragma unroll
    for (int j = 0; j < NSLOT; j++) { acc[j] = expf(acc[j] - m); ssum += acc[j]; }
    float inv = 1.0f / ssum;

    // ---------------- output: sum_j attn * (v + pe) --------------------------
    float o = acc[KNN] * g_vg[b * DIM + c];   // global slot, pe = 0
    #pragma unroll
    for (int j = 0; j < KNN; j++) {
        int pidx = knn_idx[j];
        float vj = g_vproj[(b * NPT + pidx) * DIM + c];
        o += acc[j] * (vj + pe_sh[j * DIM + c]);
    }
    out[bq * DIM + c] = o * inv;
}

// ============================================================
extern "C" void kernel_launch(void* const* d_in, const int* in_sizes, int n_in,
                              void* d_out, int out_size) {
    const float* xyz_q  = (const float*)d_in[0];
    const float* lat    = (const float*)d_in[1];
    const float* xyz    = (const float*)d_in[2];
    const float* points = (const float*)d_in[3];
    const float* w_qs   = (const float*)d_in[4];
    const float* w_ks   = (const float*)d_in[5];
    const float* w_vs   = (const float*)d_in[6];
    const float* w_kg   = (const float*)d_in[7];
    const float* w_vg   = (const float*)d_in[8];
    const float* gw1    = (const float*)d_in[9];
    const float* gb1    = (const float*)d_in[10];
    const float* gw2    = (const float*)d_in[11];
    const float* gb2    = (const float*)d_in[12];
    const float* pe_w   = (const float*)d_in[13];
    const float* pe_b   = (const float*)d_in[14];
    float* out = (float*)d_out;

    proj_global_kernel<<<BATCH, DIM>>>(lat, w_qs, w_kg, w_vg);
    proj_points_kernel<<<BATCH * NPT / PROWS, DIM>>>(points, w_ks, w_vs);
    main_kernel<<<BATCH * NQ, DIM>>>(xyz_q, xyz, gw1, gb1, gw2, gb2, pe_w, pe_b, out);
}

// round 8
// speedup vs baseline: 1.1495x; 1.1495x over previous
#include <cuda_runtime.h>
#include <math.h>

#define BATCH 2
#define NQ    8192
#define NPT   4096
#define DIM   128
#define KNN   16
#define NFEAT 33
#define NROWS_FOLD (DIM + NFEAT + 1)   // 162 rows folded through gw1

// ---- scratch (static __device__ — no allocations allowed) ----
__device__ float g_wk1 [DIM * DIM];      // w_ks @ gw1
__device__ float g_pew1[NFEAT * DIM];    // pe_w @ gw1
__device__ float g_A   [DIM];            // pe_b @ gw1
__device__ float g_nc  [BATCH * DIM];    // (lat@w_qs)@gw1 + A + gb1
__device__ float g_sglob[BATCH * DIM];   // relu((q-kg)@gw1+gb1)@gw2 + gb2
__device__ float g_vg  [BATCH * DIM];    // lat @ w_vg
__device__ float g_kw1 [BATCH * NPT * DIM]; // points @ wk1
__device__ float g_vproj[BATCH * NPT * DIM];// points @ w_vs

// ============================================================
// Kernel A: fold {w_ks rows, pe_w rows, pe_b} through gw1.
// ============================================================
__global__ __launch_bounds__(DIM)
void setup_weights(const float* __restrict__ w_ks,
                   const float* __restrict__ pe_w,
                   const float* __restrict__ pe_b,
                   const float* __restrict__ gw1) {
    int c = threadIdx.x;
    for (int r8 = 0; r8 < 8; r8++) {
        int r = blockIdx.x * 8 + r8;
        if (r >= NROWS_FOLD) return;
        const float* src = (r < DIM) ? (w_ks + r * DIM)
                         : (r < DIM + NFEAT) ? (pe_w + (r - DIM) * DIM)
                         : pe_b;
        float acc = 0.f;
        #pragma unroll 4
        for (int k = 0; k < DIM; k++)
            acc += __ldg(src + k) * gw1[k * DIM + c];
        if (r < DIM)              g_wk1 [r * DIM + c] = acc;
        else if (r < DIM + NFEAT) g_pew1[(r - DIM) * DIM + c] = acc;
        else                      g_A[c] = acc;
    }
}

// ============================================================
// Kernel B: per-batch constants (needs g_A ready).
// ============================================================
__global__ __launch_bounds__(DIM)
void setup_batch(const float* __restrict__ lat,
                 const float* __restrict__ w_qs,
                 const float* __restrict__ w_kg,
                 const float* __restrict__ w_vg,
                 const float* __restrict__ gw1, const float* __restrict__ gb1,
                 const float* __restrict__ gw2, const float* __restrict__ gb2) {
    int b = blockIdx.x, c = threadIdx.x;
    __shared__ float l[DIM], q_sh[DIM], kg_sh[DIM], tg_sh[DIM];
    l[c] = lat[b * DIM + c];
    __syncthreads();
    float aq = 0.f, ak = 0.f, av = 0.f;
    #pragma unroll 4
    for (int k = 0; k < DIM; k++) {
        float lv = l[k];
        aq += lv * w_qs[k * DIM + c];
        ak += lv * w_kg[k * DIM + c];
        av += lv * w_vg[k * DIM + c];
    }
    q_sh[c] = aq; kg_sh[c] = ak;
    g_vg[b * DIM + c] = av;
    __syncthreads();
    float qg1 = 0.f, kg1 = 0.f;
    #pragma unroll 4
    for (int k = 0; k < DIM; k++) {
        float w = gw1[k * DIM + c];
        qg1 += q_sh[k] * w;
        kg1 += kg_sh[k] * w;
    }
    g_nc[b * DIM + c] = qg1 + g_A[c] + gb1[c];
    tg_sh[c] = fmaxf(qg1 - kg1 + gb1[c], 0.f);
    __syncthreads();
    float sg = gb2[c];
    #pragma unroll 4
    for (int k = 0; k < DIM; k++)
        sg += tg_sh[k] * gw2[k * DIM + c];
    g_sglob[b * DIM + c] = sg;
}

// ============================================================
// Kernel C: point projections kw1 = points@wk1, vproj = points@w_vs
// ============================================================
#define PROWS 16
__global__ __launch_bounds__(DIM)
void proj_points_kernel(const float* __restrict__ points,
                        const float* __restrict__ wvs) {
    int c = threadIdx.x;
    int row0 = blockIdx.x * PROWS;
    __shared__ float p_sh[PROWS * DIM];
    for (int i = c; i < PROWS * DIM; i += DIM)
        p_sh[i] = points[row0 * DIM + i];
    __syncthreads();

    float ak[PROWS], av[PROWS];
    #pragma unroll
    for (int r = 0; r < PROWS; r++) { ak[r] = 0.f; av[r] = 0.f; }

    for (int k = 0; k < DIM; k++) {
        float wk = g_wk1[k * DIM + c];
        float wv = wvs[k * DIM + c];
        #pragma unroll
        for (int r = 0; r < PROWS; r++) {
            float p = p_sh[r * DIM + k];
            ak[r] += p * wk;
            av[r] += p * wv;
        }
    }
    #pragma unroll
    for (int r = 0; r < PROWS; r++) {
        g_kw1 [(row0 + r) * DIM + c] = ak[r];
        g_vproj[(row0 + r) * DIM + c] = av[r];
    }
}

// ============================================================
// Kernel D: main — one block per query, thread c = channel
// ============================================================
__global__ __launch_bounds__(DIM)
void main_kernel(const float* __restrict__ xyz_q,
                 const float* __restrict__ xyz,
                 const float* __restrict__ gw2, const float* __restrict__ gb2,
                 const float* __restrict__ pe_w, const float* __restrict__ pe_b,
                 float* __restrict__ out) {
    // pool layout: [0:2048) t_sh | [2048:4096) pe_sh | [4096:4624) emb
    // kNN candidate lists (128*16 dist + 128*16 idx) alias [0:4096).
    __shared__ float pool[4096 + 544];
    __shared__ int   knn_idx[KNN];
    float* t_sh   = pool;
    float* pe_sh  = pool + 2048;
    float* emb_sh = pool + 4096;

    const int tid = threadIdx.x;
    const int bq  = blockIdx.x;
    const int b   = bq / NQ;

    const float qx = xyz_q[bq * 2 + 0];
    const float qy = xyz_q[bq * 2 + 1];
    const float* xyzb = xyz + b * NPT * 3;

    // ---------------- kNN: per-thread top-16 over 32 points ----------------
    float bd[KNN]; int bi[KNN];
    #pragma unroll
    for (int k = 0; k < KNN; k++) { bd[k] = 3.4e38f; bi[k] = 0; }

    for (int p = tid; p < NPT; p += DIM) {
        float dx = qx - xyzb[p * 3 + 0];
        float dy = qy - xyzb[p * 3 + 1];
        float d  = dx * dx + dy * dy;
        if (d < bd[KNN - 1]) {
            bd[KNN - 1] = d; bi[KNN - 1] = p;
            #pragma unroll
            for (int s = KNN - 1; s > 0; s--) {
                if (bd[s] < bd[s - 1]) {
                    float td = bd[s]; bd[s] = bd[s - 1]; bd[s - 1] = td;
                    int   ti = bi[s]; bi[s] = bi[s - 1]; bi[s - 1] = ti;
                }
            }
        }
    }

    float* cd = pool;                 // 2048 floats
    int*   ci = (int*)(pool + 2048);  // 2048 ints
    #pragma unroll
    for (int k = 0; k < KNN; k++) { cd[tid * KNN + k] = bd[k]; ci[tid * KNN + k] = bi[k]; }
    __syncthreads();

    for (int stride = 64; stride >= 1; stride >>= 1) {
        if (tid < stride) {
            int a0 = tid * KNN, b0 = (tid + stride) * KNN;
            int ia = 0, ib = 0;
            float od[KNN]; int oi[KNN];
            #pragma unroll
            for (int k = 0; k < KNN; k++) {
                float da = (ia < KNN) ? cd[a0 + ia] : 3.4e38f;
                float db = (ib < KNN) ? cd[b0 + ib] : 3.4e38f;
                if (da <= db) { od[k] = da; oi[k] = ci[a0 + ia]; ia++; }
                else          { od[k] = db; oi[k] = ci[b0 + ib]; ib++; }
            }
            #pragma unroll
            for (int k = 0; k < KNN; k++) { cd[a0 + k] = od[k]; ci[a0 + k] = oi[k]; }
        }
        __syncthreads();
    }
    if (tid < KNN) knn_idx[tid] = ci[tid];
    __syncthreads();

    // ---------------- positional embeddings (16 neighbors x 33 feats) ------
    if (tid < KNN * 3) {
        int j = tid / 3, comp = tid - j * 3;
        int pidx = knn_idx[j];
        float v;
        if      (comp == 0) v = qx - xyzb[pidx * 3 + 0];
        else if (comp == 1) v = qy - xyzb[pidx * 3 + 1];
        else                v = xyzb[pidx * 3 + 2];
        emb_sh[j * NFEAT + comp] = v;
        #pragma unroll
        for (int f = 0; f < 5; f++) {
            float fr = 1.0f + 7.75f * (float)f;   // linspace(1, 32, 5)
            float s, co;
            sincosf(v * fr, &s, &co);
            emb_sh[j * NFEAT + 3 + 6 * f + comp] = s;
            emb_sh[j * NFEAT + 6 + 6 * f + comp] = co;
        }
    }
    __syncthreads();

    const int c = tid;

    // ---- s1 (pre-relu GEMM1, folded) + pe, both 33-depth ----
    float a[KNN], p[KNN];
    {
        const float ncv = g_nc[b * DIM + c];
        const float peb = pe_b[c];
        #pragma unroll
        for (int j = 0; j < KNN; j++) {
            int pidx = knn_idx[j];
            a[j] = ncv - g_kw1[(b * NPT + pidx) * DIM + c];
            p[j] = peb;
        }
        for (int f = 0; f < NFEAT; f++) {
            float w1 = g_pew1[f * DIM + c];
            float w0 = pe_w [f * DIM + c];
            #pragma unroll
            for (int j = 0; j < KNN; j++) {
                float e = emb_sh[j * NFEAT + f];
                a[j] += e * w1;
                p[j] += e * w0;
            }
        }
    }
    #pragma unroll
    for (int j = 0; j < KNN; j++) {
        t_sh [j * DIM + c] = fmaxf(a[j], 0.f);
        pe_sh[j * DIM + c] = p[j];
    }
    __syncthreads();

    // ---------------- GEMM2: s2 = t @ gw2 + gb2 (16 slots) ------------------
    float acc[KNN];
    {
        float b2 = gb2[c];
        #pragma unroll
        for (int j = 0; j < KNN; j++) acc[j] = b2;
        for (int k = 0; k < DIM; k += 4) {
            float w0 = gw2[(k + 0) * DIM + c];
            float w1 = gw2[(k + 1) * DIM + c];
            float w2 = gw2[(k + 2) * DIM + c];
            float w3 = gw2[(k + 3) * DIM + c];
            #pragma unroll
            for (int j = 0; j < KNN; j++) {
                float4 tv = *(const float4*)&t_sh[j * DIM + k];
                acc[j] += tv.x * w0 + tv.y * w1 + tv.z * w2 + tv.w * w3;
            }
        }
    }

    // ---------------- softmax over 16 neighbors + global slot ---------------
    float sg = g_sglob[b * DIM + c];
    float m = sg;
    #pragma unroll
    for (int j = 0; j < KNN; j++) m = fmaxf(m, acc[j]);
    float ssum = expf(sg - m);
    float eg = ssum;
    #pragma unroll
    for (int j = 0; j < KNN; j++) { acc[j] = expf(acc[j] - m); ssum += acc[j]; }
    float inv = 1.0f / ssum;

    // ---------------- output ------------------------------------------------
    float o = eg * g_vg[b * DIM + c];
    #pragma unroll
    for (int j = 0; j < KNN; j++) {
        int pidx = knn_idx[j];
        float vj = g_vproj[(b * NPT + pidx) * DIM + c];
        o += acc[j] * (vj + pe_sh[j * DIM + c]);
    }
    out[bq * DIM + c] = o * inv;
}

// ============================================================
extern "C" void kernel_launch(void* const* d_in, const int* in_sizes, int n_in,
                              void* d_out, int out_size) {
    const float* xyz_q  = (const float*)d_in[0];
    const float* lat    = (const float*)d_in[1];
    const float* xyz    = (const float*)d_in[2];
    const float* points = (const float*)d_in[3];
    const float* w_qs   = (const float*)d_in[4];
    const float* w_ks   = (const float*)d_in[5];
    const float* w_vs   = (const float*)d_in[6];
    const float* w_kg   = (const float*)d_in[7];
    const float* w_vg   = (const float*)d_in[8];
    const float* gw1    = (const float*)d_in[9];
    const float* gb1    = (const float*)d_in[10];
    const float* gw2    = (const float*)d_in[11];
    const float* gb2    = (const float*)d_in[12];
    const float* pe_w   = (const float*)d_in[13];
    const float* pe_b   = (const float*)d_in[14];
    float* out = (float*)d_out;

    setup_weights<<<(NROWS_FOLD + 7) / 8, DIM>>>(w_ks, pe_w, pe_b, gw1);
    setup_batch<<<BATCH, DIM>>>(lat, w_qs, w_kg, w_vg, gw1, gb1, gw2, gb2);
    proj_points_kernel<<<BATCH * NPT / PROWS, DIM>>>(points, w_vs);
    main_kernel<<<BATCH * NQ, DIM>>>(xyz_q, xyz, gw2, gb2, pe_w, pe_b, out);
}